// round 16
// baseline (speedup 1.0000x reference)
#include <cuda_runtime.h>
#include <cuda_fp16.h>
#include <cstdint>

// ============================================================
// LSTMCell: B=8192, I=1024, H=1024, C=2048, 4H=4096
// Single-pass fp16 mma.sync GEMM, f32 accumulators (sm_103 SIMT
// HMMA rt16). CTA 128x256 / 512 threads (16 warps, 4/SMSP),
// warp tile 32x64, BK=32, 5-stage pipeline, barrier per 2 ktiles.
// A=[x|h] is converted fp32->fp16 INLINE in the GEMM loader
// (LDG.128 + F2FP + STS.128, 1-stage register pending buffer);
// only W needs a prepass (gate-interleaved, row p=4j+gate).
// LSTM activations fused into the GEMM epilogue.
// ============================================================
#define B_DIM 8192
#define H_DIM 1024
#define C_DIM 2048
#define G_DIM 4096

__device__ __half g_W[(size_t)G_DIM * C_DIM];   // permuted stacked W fp16

// ============================================================
// PTX helpers (sm_80-baseline; legal at compute_103)
// ============================================================
__device__ __forceinline__ uint32_t smem_to_u32(const void* p) {
    uint32_t a;
    asm("{ .reg .u64 t; cvta.to.shared.u64 t, %1; cvt.u32.u64 %0, t; }" : "=r"(a) : "l"(p));
    return a;
}
__device__ __forceinline__ void cp_async16(uint32_t saddr, const void* gaddr) {
    asm volatile("cp.async.cg.shared.global [%0], [%1], 16;" :: "r"(saddr), "l"(gaddr));
}
#define CP_COMMIT() asm volatile("cp.async.commit_group;" ::: "memory")
#define CP_WAIT1()  asm volatile("cp.async.wait_group 1;" ::: "memory")

__device__ __forceinline__ void ldsm4(uint32_t& r0, uint32_t& r1, uint32_t& r2, uint32_t& r3,
                                      uint32_t addr) {
    asm volatile("ldmatrix.sync.aligned.m8n8.x4.shared.b16 {%0,%1,%2,%3}, [%4];"
                 : "=r"(r0), "=r"(r1), "=r"(r2), "=r"(r3) : "r"(addr));
}
__device__ __forceinline__ void mma_fp16(float* c, const uint32_t* a, uint32_t b0, uint32_t b1) {
    asm volatile(
        "mma.sync.aligned.m16n8k16.row.col.f32.f16.f16.f32 "
        "{%0,%1,%2,%3}, {%4,%5,%6,%7}, {%8,%9}, {%0,%1,%2,%3};"
        : "+f"(c[0]), "+f"(c[1]), "+f"(c[2]), "+f"(c[3])
        : "r"(a[0]), "r"(a[1]), "r"(a[2]), "r"(a[3]), "r"(b0), "r"(b1));
}
__device__ __forceinline__ uint32_t h2_bits(__half2 v) {
    return *reinterpret_cast<uint32_t*>(&v);
}

// ============================================================
// Prepass (W only): row p = 4*j + gate  (gate: 0=i,1=f,2=o,3=g)
// 8 elements / thread.
// ============================================================
#define PREP_TPB 256
#define W_CHUNKS ((size_t)G_DIM * C_DIM / 8)      // 1048576
#define W_BLOCKS (W_CHUNKS / PREP_TPB)            // 4096

__global__ void prep_W_kernel(const float* __restrict__ Wi, const float* __restrict__ Wf,
                              const float* __restrict__ Wo, const float* __restrict__ Wg) {
    size_t idx = (size_t)blockIdx.x * blockDim.x + threadIdx.x;
    size_t base = idx * 8;
    size_t p = base >> 11;
    int    k = (int)(base & 2047);
    int gate = (int)(p & 3);
    size_t j = p >> 2;
    const float* W = (gate == 0) ? Wi : (gate == 1) ? Wf : (gate == 2) ? Wo : Wg;
    const float* src = W + j * 2048 + k;
    float4 v0 = *(const float4*)(src);
    float4 v1 = *(const float4*)(src + 4);
    uint4 o;
    o.x = h2_bits(__floats2half2_rn(v0.x, v0.y));
    o.y = h2_bits(__floats2half2_rn(v0.z, v0.w));
    o.z = h2_bits(__floats2half2_rn(v1.x, v1.y));
    o.w = h2_bits(__floats2half2_rn(v1.z, v1.w));
    *(uint4*)(g_W + base) = o;
}

// ============================================================
// GEMM + fused LSTM epilogue
// ============================================================
#define BM 128
#define BN 256
#define BK 32
#define NTHREADS 512
#define STAGES 5
#define PFD 3                                     // prefetch distance
#define SA 40                                     // halves per smem row
#define A_BYTES (BM * SA * 2)                     // 10240
#define W_BYTES (BN * SA * 2)                     // 20480
#define STAGE_BYTES (A_BYTES + W_BYTES)           // 30720
#define SMEM_TOTAL (STAGES * STAGE_BYTES)         // 153600
#define KT (C_DIM / BK)                           // 64 (even)
#define SROW 260                                  // epilogue smem stride (floats)

__global__ void __launch_bounds__(NTHREADS, 1) lstm_gemm_kernel(
    const float* __restrict__ x,  const float* __restrict__ h,
    const float* __restrict__ cin,
    const float* __restrict__ bi, const float* __restrict__ bf_,
    const float* __restrict__ bo, const float* __restrict__ bg,
    float* __restrict__ out)
{
    extern __shared__ __align__(128) char smem[];
    const uint32_t sb = smem_to_u32(smem);
    const int tid = threadIdx.x;
    const int m0 = blockIdx.x * BM;
    const int n0 = blockIdx.y * BN;
    const int l = tid & 31, w = tid >> 5;
    const int wm = w >> 2, wn = w & 3;            // 4(M) x 4(N); warp tile 32x64

    const __half* gW = g_W + (size_t)n0 * C_DIM;

    const uint32_t a_off = (uint32_t)((wm * 32 + (l & 15)) * SA + (l >> 4) * 8) * 2;
    const uint32_t b_off = (uint32_t)((wn * 64 + (l & 15)) * SA + (l >> 4) * 8) * 2;

    float acc[2][8][4];
#pragma unroll
    for (int i = 0; i < 2; i++)
#pragma unroll
        for (int j = 0; j < 8; j++)
#pragma unroll
            for (int r = 0; r < 4; r++) acc[i][j][r] = 0.0f;

    // ---- A loader: fp32 gmem -> regs -> fp16 smem (1 chunk = 8 elems/thread) ----
    const int arow = tid >> 2, aseg = tid & 3;
    const uint32_t a_soff = (uint32_t)(arow * SA + aseg * 8) * 2;
    // bases include the per-thread aseg*8 element offset
    const float* xbase = x + (size_t)(m0 + arow) * 1024 + aseg * 8;
    const float* hbase = h + (size_t)(m0 + arow) * 1024 + aseg * 8 - 1024;
    // an 8-float chunk never straddles the x|h seam (8-aligned within 2048)
    auto ldgA = [&](int kt, float4& p0, float4& p1) {
        const int kidx = kt * BK + aseg * 8;
        const float* s = (kidx < 1024) ? (xbase + kt * BK) : (hbase + kt * BK);
        p0 = *(const float4*)(s);
        p1 = *(const float4*)(s + 4);
    };
    auto stsA = [&](int slot, const float4& p0, const float4& p1) {
        uint4 o;
        o.x = h2_bits(__floats2half2_rn(p0.x, p0.y));
        o.y = h2_bits(__floats2half2_rn(p0.z, p0.w));
        o.z = h2_bits(__floats2half2_rn(p1.x, p1.y));
        o.w = h2_bits(__floats2half2_rn(p1.z, p1.w));
        *(uint4*)(smem + (size_t)slot * STAGE_BYTES + a_soff) = o;
    };

    // ---- W loader via cp.async: 2 chunks/thread/stage (group = W only) ----
    const int wrow0 = (tid * 2) >> 2, wseg0 = (tid * 2) & 3;
    const int wrow1 = (tid * 2 + 1) >> 2, wseg1 = (tid * 2 + 1) & 3;
    const uint32_t w_soff0 = (uint32_t)(wrow0 * SA + wseg0 * 8) * 2;
    const uint32_t w_soff1 = (uint32_t)(wrow1 * SA + wseg1 * 8) * 2;
    const size_t   w_goff0 = (size_t)wrow0 * C_DIM + wseg0 * 8;
    const size_t   w_goff1 = (size_t)wrow1 * C_DIM + wseg1 * 8;
    auto load_W = [&](int slot, int kt) {
        const int k0 = kt * BK;
        const uint32_t sbase = sb + slot * STAGE_BYTES + A_BYTES;
        cp_async16(sbase + w_soff0, gW + w_goff0 + k0);
        cp_async16(sbase + w_soff1, gW + w_goff1 + k0);
    };

    // ---- prologue: stages 0..2 + pending stage 3; LDGs overlap ----
    float4 a00, a01, a10, a11, a20, a21, pen0, pen1;
    ldgA(0, a00, a01);
    ldgA(1, a10, a11);
    ldgA(2, a20, a21);
    ldgA(3, pen0, pen1);
    load_W(0, 0); CP_COMMIT();
    load_W(1, 1); CP_COMMIT();
    load_W(2, 2); CP_COMMIT();
    stsA(0, a00, a01);
    stsA(1, a10, a11);
    stsA(2, a20, a21);

    for (int i = 0; i < KT; i++) {
        // Even iters: wait for W of stages i AND i+1; one barrier publishes
        // both (and all A STS fills issued at iters <= i-1 / prologue).
        // Fill at iter i targets the slot consumed at i-2; the even-only
        // barrier always intervenes between that consume and this fill.
        if ((i & 1) == 0) {
            CP_WAIT1();
            __syncthreads();
        }
        const int pf = i + PFD;
        if (pf < KT) {
            stsA(pf % STAGES, pen0, pen1);        // A fill for stage pf
            load_W(pf % STAGES, pf);              // W fill for stage pf
        }
        CP_COMMIT();                              // uniform group count
        if (pf + 1 < KT) ldgA(pf + 1, pen0, pen1);

        const uint32_t sbase = sb + (i % STAGES) * STAGE_BYTES;
        const uint32_t aA = sbase + a_off;
        const uint32_t aW = sbase + A_BYTES + b_off;

#pragma unroll
        for (int k16 = 0; k16 < 2; k16++) {
            const uint32_t kd = (uint32_t)(k16 * 16) * 2;
            uint32_t Af[2][4], Bf[4][4];
#pragma unroll
            for (int mt = 0; mt < 2; mt++) {
                const uint32_t md = (uint32_t)(mt * 16 * SA) * 2;
                ldsm4(Af[mt][0], Af[mt][1], Af[mt][2], Af[mt][3], aA + md + kd);
            }
#pragma unroll
            for (int ntp = 0; ntp < 4; ntp++) {
                const uint32_t nd = (uint32_t)(ntp * 16 * SA) * 2;
                ldsm4(Bf[ntp][0], Bf[ntp][1], Bf[ntp][2], Bf[ntp][3], aW + nd + kd);
            }
#pragma unroll
            for (int mt = 0; mt < 2; mt++)
#pragma unroll
                for (int nt = 0; nt < 8; nt++) {
                    const int p = nt >> 1, q = nt & 1;
                    mma_fp16(acc[mt][nt], Af[mt], Bf[p][q], Bf[p][q + 2]);
                }
        }
    }

    // ---- fused epilogue in two 64-row halves (smem reuse) ----
    // half 0 = rows 0..63 (warps wm 0,1), half 1 = rows 64..127 (wm 2,3)
    float* sout = (float*)smem;
    const int jl = tid & 63;                      // local h-col 0..63
    const int rg = tid >> 6;                      // 8 row groups
    const int jg = (n0 >> 2) + jl;                // global h-col
    const float Bi = bi[jg], Bff = bf_[jg], Bo = bo[jg], Bg = bg[jg];
    __syncthreads();

#pragma unroll
    for (int half = 0; half < 2; half++) {
        // prefetch cin for this half (hides DRAM latency behind staging+barrier)
        float cpre[8];
#pragma unroll
        for (int rep = 0; rep < 8; rep++) {
            const int row = rg + rep * 8;
            cpre[rep] = cin[(size_t)(m0 + half * 64 + row) * H_DIM + jg];
        }

        if ((wm >> 1) == half) {
            const int lrow_base = (wm & 1) * 32;
#pragma unroll
            for (int mt = 0; mt < 2; mt++) {
                const int row0 = lrow_base + mt * 16 + (l >> 2);   // local 0..63
#pragma unroll
                for (int nt = 0; nt < 8; nt++) {
                    const int col = wn * 64 + nt * 8 + (l & 3) * 2;
                    *(float2*)&sout[(size_t)row0 * SROW + col] =
                        make_float2(acc[mt][nt][0], acc[mt][nt][1]);
                    *(float2*)&sout[(size_t)(row0 + 8) * SROW + col] =
                        make_float2(acc[mt][nt][2], acc[mt][nt][3]);
                }
            }
        }
        __syncthreads();

#pragma unroll
        for (int rep = 0; rep < 8; rep++) {
            const int row = rg + rep * 8;                      // local 0..63
            float4 q = *(float4*)&sout[(size_t)row * SROW + 4 * jl];
            const float ip = q.x + Bi;
            const float fp = q.y + Bff;
            const float op = q.z + Bo;
            const float gp = q.w + Bg;
            const float iv = 1.0f / (1.0f + __expf(-ip));
            const float fv = 1.0f / (1.0f + __expf(-fp));
            const float ov = 1.0f / (1.0f + __expf(-op));
            const float gv = 1.0f - 2.0f / (__expf(2.0f * gp) + 1.0f);
            const size_t gidx = (size_t)(m0 + half * 64 + row) * H_DIM + jg;
            const float ct = fv * cpre[rep] + iv * gv;
            const float th = 1.0f - 2.0f / (__expf(2.0f * ct) + 1.0f);
            out[gidx] = ov * th;                               // h_t
            out[(size_t)B_DIM * H_DIM + gidx] = ct;            // c_t
        }
        __syncthreads();
    }
}

// ============================================================
// kernel_launch
// Inputs: x, h, c, W_i, W_f, W_o, W_g, b_i, b_f, b_o, b_g
// Output: [h_t (B*H) | c_t (B*H)] fp32
// ============================================================
extern "C" void kernel_launch(void* const* d_in, const int* in_sizes, int n_in,
                              void* d_out, int out_size) {
    const float* x  = (const float*)d_in[0];
    const float* h  = (const float*)d_in[1];
    const float* c  = (const float*)d_in[2];
    const float* Wi = (const float*)d_in[3];
    const float* Wf = (const float*)d_in[4];
    const float* Wo = (const float*)d_in[5];
    const float* Wg = (const float*)d_in[6];
    const float* bi = (const float*)d_in[7];
    const float* bf_ = (const float*)d_in[8];
    const float* bo = (const float*)d_in[9];
    const float* bg = (const float*)d_in[10];
    float* out = (float*)d_out;

    cudaFuncSetAttribute(lstm_gemm_kernel,
                         cudaFuncAttributeMaxDynamicSharedMemorySize, SMEM_TOTAL);

    {   // prepass: W only (A converts inline in the GEMM)
        prep_W_kernel<<<(unsigned)W_BLOCKS, PREP_TPB>>>(Wi, Wf, Wo, Wg);
    }
    {   // GEMM + fused epilogue
        dim3 grid(B_DIM / BM, G_DIM / BN);
        lstm_gemm_kernel<<<grid, NTHREADS, SMEM_TOTAL>>>(x, h, c, bi, bf_, bo, bg, out);
    }
}

// round 17
// speedup vs baseline: 1.0421x; 1.0421x over previous
#include <cuda_runtime.h>
#include <cuda_fp16.h>
#include <cstdint>

// ============================================================
// LSTMCell: B=8192, I=1024, H=1024, C=2048, 4H=4096
// Single-pass fp16 mma.sync GEMM (tcgen05 unavailable at
// compute_103). CTA 128x256 / 512 threads (16 warps, 4/SMSP),
// warp tile 32x64, BK=32, 5-stage cp.async (prefetch dist 3),
// ONE barrier per 2 ktiles. W gate-interleaved (row p=4j+gate):
// LSTM activations fused into the GEMM epilogue.
// FINAL: measured optimum (R12 = 478.3us); all perturbations
// (BK=64, reg dbuf, x2 unroll, 6 stages, f16-accum, inline-A)
// regressed. GEMM is ~99% of the sm_103 HMMA rt16 issue floor.
// ============================================================
#define B_DIM 8192
#define H_DIM 1024
#define C_DIM 2048
#define G_DIM 4096

__device__ __half g_A[(size_t)B_DIM * C_DIM];   // [x|h] fp16
__device__ __half g_W[(size_t)G_DIM * C_DIM];   // permuted stacked W fp16

// ============================================================
// PTX helpers (sm_80-baseline; legal at compute_103)
// ============================================================
__device__ __forceinline__ uint32_t smem_to_u32(const void* p) {
    uint32_t a;
    asm("{ .reg .u64 t; cvta.to.shared.u64 t, %1; cvt.u32.u64 %0, t; }" : "=r"(a) : "l"(p));
    return a;
}
__device__ __forceinline__ void cp_async16(uint32_t saddr, const void* gaddr) {
    asm volatile("cp.async.cg.shared.global [%0], [%1], 16;" :: "r"(saddr), "l"(gaddr));
}
#define CP_COMMIT() asm volatile("cp.async.commit_group;" ::: "memory")
#define CP_WAIT1()  asm volatile("cp.async.wait_group 1;" ::: "memory")

__device__ __forceinline__ void ldsm4(uint32_t& r0, uint32_t& r1, uint32_t& r2, uint32_t& r3,
                                      uint32_t addr) {
    asm volatile("ldmatrix.sync.aligned.m8n8.x4.shared.b16 {%0,%1,%2,%3}, [%4];"
                 : "=r"(r0), "=r"(r1), "=r"(r2), "=r"(r3) : "r"(addr));
}
__device__ __forceinline__ void mma_fp16(float* c, const uint32_t* a, uint32_t b0, uint32_t b1) {
    asm volatile(
        "mma.sync.aligned.m16n8k16.row.col.f32.f16.f16.f32 "
        "{%0,%1,%2,%3}, {%4,%5,%6,%7}, {%8,%9}, {%0,%1,%2,%3};"
        : "+f"(c[0]), "+f"(c[1]), "+f"(c[2]), "+f"(c[3])
        : "r"(a[0]), "r"(a[1]), "r"(a[2]), "r"(a[3]), "r"(b0), "r"(b1));
}
__device__ __forceinline__ uint32_t h2_bits(__half2 v) {
    return *reinterpret_cast<uint32_t*>(&v);
}

// ============================================================
// Merged prepass: one launch converts A (=[x|h]) and permuted W.
// ============================================================
#define PREP_TPB 256
#define A_CHUNKS ((size_t)B_DIM * C_DIM / 8)
#define W_CHUNKS ((size_t)G_DIM * C_DIM / 8)
#define A_BLOCKS (A_CHUNKS / PREP_TPB)            // 8192
#define W_BLOCKS (W_CHUNKS / PREP_TPB)            // 4096

__global__ void prep_kernel(const float* __restrict__ x, const float* __restrict__ h,
                            const float* __restrict__ Wi, const float* __restrict__ Wf,
                            const float* __restrict__ Wo, const float* __restrict__ Wg) {
    const unsigned b = blockIdx.x;
    const float* src;
    __half* dst;
    size_t base;
    if (b < A_BLOCKS) {
        size_t idx = (size_t)b * PREP_TPB + threadIdx.x;
        base = idx * 8;
        size_t r = base >> 11;
        int    k = (int)(base & 2047);
        src = (k < 1024) ? (x + r * 1024 + k) : (h + r * 1024 + (k - 1024));
        dst = g_A + base;
    } else {
        size_t idx = (size_t)(b - A_BLOCKS) * PREP_TPB + threadIdx.x;
        base = idx * 8;
        size_t p = base >> 11;
        int    k = (int)(base & 2047);
        int gate = (int)(p & 3);                  // row p = 4*j + gate
        size_t j = p >> 2;
        const float* W = (gate == 0) ? Wi : (gate == 1) ? Wf : (gate == 2) ? Wo : Wg;
        src = W + j * 2048 + k;
        dst = g_W + base;
    }
    float4 v0 = *(const float4*)(src);
    float4 v1 = *(const float4*)(src + 4);
    uint4 o;
    o.x = h2_bits(__floats2half2_rn(v0.x, v0.y));
    o.y = h2_bits(__floats2half2_rn(v0.z, v0.w));
    o.z = h2_bits(__floats2half2_rn(v1.x, v1.y));
    o.w = h2_bits(__floats2half2_rn(v1.z, v1.w));
    *(uint4*)dst = o;
}

// ============================================================
// GEMM + fused LSTM epilogue
// ============================================================
#define BM 128
#define BN 256
#define BK 32
#define NTHREADS 512
#define STAGES 5
#define PFD (STAGES - 2)                          // prefetch distance 3
#define SA 40                                     // halves per smem row
#define A_BYTES (BM * SA * 2)                     // 10240
#define W_BYTES (BN * SA * 2)                     // 20480
#define STAGE_BYTES (A_BYTES + W_BYTES)           // 30720
#define SMEM_TOTAL (STAGES * STAGE_BYTES)         // 153600
#define KT (C_DIM / BK)                           // 64
#define SROW 260                                  // epilogue smem stride (floats)

__global__ void __launch_bounds__(NTHREADS, 1) lstm_gemm_kernel(
    const float* __restrict__ cin,
    const float* __restrict__ bi, const float* __restrict__ bf_,
    const float* __restrict__ bo, const float* __restrict__ bg,
    float* __restrict__ out)
{
    extern __shared__ __align__(128) char smem[];
    const uint32_t sb = smem_to_u32(smem);
    const int tid = threadIdx.x;
    const int m0 = blockIdx.x * BM;
    const int n0 = blockIdx.y * BN;
    const int l = tid & 31, w = tid >> 5;
    const int wm = w >> 2, wn = w & 3;            // 4(M) x 4(N); warp tile 32x64

    const __half* gA = g_A + (size_t)m0 * C_DIM;
    const __half* gW = g_W + (size_t)n0 * C_DIM;

    const uint32_t a_off = (uint32_t)((wm * 32 + (l & 15)) * SA + (l >> 4) * 8) * 2;
    const uint32_t b_off = (uint32_t)((wn * 64 + (l & 15)) * SA + (l >> 4) * 8) * 2;

    float acc[2][8][4];
#pragma unroll
    for (int i = 0; i < 2; i++)
#pragma unroll
        for (int j = 0; j < 8; j++)
#pragma unroll
            for (int r = 0; r < 4; r++) acc[i][j][r] = 0.0f;

    // Per stage: A = 512 16B-chunks (1/thread), W = 1024 (2/thread)
    auto load_stage = [&](int slot, int kt) {
        const int k0 = kt * BK;
        const uint32_t sbase = sb + slot * STAGE_BYTES;
        {
            const int c = tid;
            const int row = c >> 2, seg = c & 3;
            cp_async16(sbase + (uint32_t)(row * SA + seg * 8) * 2,
                       gA + (size_t)row * C_DIM + k0 + seg * 8);
        }
#pragma unroll
        for (int j = 0; j < 2; j++) {
            const int c = tid * 2 + j;
            const int row = c >> 2, seg = c & 3;
            cp_async16(sbase + A_BYTES + (uint32_t)(row * SA + seg * 8) * 2,
                       gW + (size_t)row * C_DIM + k0 + seg * 8);
        }
    };

    // Prologue: fill stages 0..PFD-1
#pragma unroll
    for (int s = 0; s < PFD; s++) { load_stage(s, s); CP_COMMIT(); }

    for (int i = 0; i < KT; i++) {
        // Even iters: wait for stages i AND i+1, one barrier covers both.
        // Refill at iter i overwrites data consumed at i-2 (PFD=3, 5 slots);
        // the even-only barrier still covers that reuse.
        if ((i & 1) == 0) {
            CP_WAIT1();
            __syncthreads();
        }
        const int pf = i + PFD;
        if (pf < KT) load_stage(pf % STAGES, pf);
        CP_COMMIT();                     // uniform group count

        const uint32_t sbase = sb + (i % STAGES) * STAGE_BYTES;
        const uint32_t aA = sbase + a_off;
        const uint32_t aW = sbase + A_BYTES + b_off;

#pragma unroll
        for (int k16 = 0; k16 < 2; k16++) {
            const uint32_t kd = (uint32_t)(k16 * 16) * 2;
            uint32_t Af[2][4], Bf[4][4];
#pragma unroll
            for (int mt = 0; mt < 2; mt++) {
                const uint32_t md = (uint32_t)(mt * 16 * SA) * 2;
                ldsm4(Af[mt][0], Af[mt][1], Af[mt][2], Af[mt][3], aA + md + kd);
            }
#pragma unroll
            for (int ntp = 0; ntp < 4; ntp++) {
                const uint32_t nd = (uint32_t)(ntp * 16 * SA) * 2;
                ldsm4(Bf[ntp][0], Bf[ntp][1], Bf[ntp][2], Bf[ntp][3], aW + nd + kd);
            }
#pragma unroll
            for (int mt = 0; mt < 2; mt++)
#pragma unroll
                for (int nt = 0; nt < 8; nt++) {
                    const int p = nt >> 1, q = nt & 1;
                    mma_fp16(acc[mt][nt], Af[mt], Bf[p][q], Bf[p][q + 2]);
                }
        }
    }

    // ---- fused epilogue in two 64-row halves (smem reuse) ----
    // half 0 = rows 0..63 (warps wm 0,1), half 1 = rows 64..127 (wm 2,3)
    float* sout = (float*)smem;
    const int jl = tid & 63;                      // local h-col 0..63
    const int rg = tid >> 6;                      // 8 row groups
    const int jg = (n0 >> 2) + jl;                // global h-col
    const float Bi = bi[jg], Bff = bf_[jg], Bo = bo[jg], Bg = bg[jg];
    __syncthreads();

#pragma unroll
    for (int half = 0; half < 2; half++) {
        // prefetch cin for this half (hides DRAM latency behind staging+barrier)
        float cpre[8];
#pragma unroll
        for (int rep = 0; rep < 8; rep++) {
            const int row = rg + rep * 8;
            cpre[rep] = cin[(size_t)(m0 + half * 64 + row) * H_DIM + jg];
        }

        if ((wm >> 1) == half) {
            const int lrow_base = (wm & 1) * 32;
#pragma unroll
            for (int mt = 0; mt < 2; mt++) {
                const int row0 = lrow_base + mt * 16 + (l >> 2);   // local 0..63
#pragma unroll
                for (int nt = 0; nt < 8; nt++) {
                    const int col = wn * 64 + nt * 8 + (l & 3) * 2;
                    *(float2*)&sout[(size_t)row0 * SROW + col] =
                        make_float2(acc[mt][nt][0], acc[mt][nt][1]);
                    *(float2*)&sout[(size_t)(row0 + 8) * SROW + col] =
                        make_float2(acc[mt][nt][2], acc[mt][nt][3]);
                }
            }
        }
        __syncthreads();

#pragma unroll
        for (int rep = 0; rep < 8; rep++) {
            const int row = rg + rep * 8;                      // local 0..63
            float4 q = *(float4*)&sout[(size_t)row * SROW + 4 * jl];
            const float ip = q.x + Bi;
            const float fp = q.y + Bff;
            const float op = q.z + Bo;
            const float gp = q.w + Bg;
            const float iv = 1.0f / (1.0f + __expf(-ip));
            const float fv = 1.0f / (1.0f + __expf(-fp));
            const float ov = 1.0f / (1.0f + __expf(-op));
            const float gv = 1.0f - 2.0f / (__expf(2.0f * gp) + 1.0f);
            const size_t gidx = (size_t)(m0 + half * 64 + row) * H_DIM + jg;
            const float ct = fv * cpre[rep] + iv * gv;
            const float th = 1.0f - 2.0f / (__expf(2.0f * ct) + 1.0f);
            out[gidx] = ov * th;                               // h_t
            out[(size_t)B_DIM * H_DIM + gidx] = ct;            // c_t
        }
        __syncthreads();
    }
}

// ============================================================
// kernel_launch
// Inputs: x, h, c, W_i, W_f, W_o, W_g, b_i, b_f, b_o, b_g
// Output: [h_t (B*H) | c_t (B*H)] fp32
// ============================================================
extern "C" void kernel_launch(void* const* d_in, const int* in_sizes, int n_in,
                              void* d_out, int out_size) {
    const float* x  = (const float*)d_in[0];
    const float* h  = (const float*)d_in[1];
    const float* c  = (const float*)d_in[2];
    const float* Wi = (const float*)d_in[3];
    const float* Wf = (const float*)d_in[4];
    const float* Wo = (const float*)d_in[5];
    const float* Wg = (const float*)d_in[6];
    const float* bi = (const float*)d_in[7];
    const float* bf_ = (const float*)d_in[8];
    const float* bo = (const float*)d_in[9];
    const float* bg = (const float*)d_in[10];
    float* out = (float*)d_out;

    cudaFuncSetAttribute(lstm_gemm_kernel,
                         cudaFuncAttributeMaxDynamicSharedMemorySize, SMEM_TOTAL);

    {   // merged prepass: A then W regions in one launch
        prep_kernel<<<(unsigned)(A_BLOCKS + W_BLOCKS), PREP_TPB>>>(x, h, Wi, Wf, Wo, Wg);
    }
    {   // GEMM + fused epilogue
        dim3 grid(B_DIM / BM, G_DIM / BN);
        lstm_gemm_kernel<<<grid, NTHREADS, SMEM_TOTAL>>>(c, bi, bf_, bo, bg, out);
    }
}